// round 12
// baseline (speedup 1.0000x reference)
#include <cuda_runtime.h>

#define NPTS 4096
#define NB   8
#define KNN  20
#define CO   64
#define CTA  256
#define ITER  16            // point-iterations per thread
#define PREI  2             // calibration iterations (512 points)
#define CAP   2048          // candidate buffer
#define TIE_CAP 128

__device__ float4 g_xp[NB * NPTS];   // {x, y, z, -0.5*|p|^2}
__device__ float4 g_wf[CO * 2];      // per o: {w0,w1,w2,w3}, {w4,w5,inv,shift}

__global__ void prep_kernel(const float* __restrict__ x,
                            const float* __restrict__ W,
                            const float* __restrict__ gamma_,
                            const float* __restrict__ beta_,
                            const float* __restrict__ mean_,
                            const float* __restrict__ var_)
{
    int idx = blockIdx.x * blockDim.x + threadIdx.x;
    if (idx < NB * NPTS) {
        int b = idx >> 12, p = idx & (NPTS - 1);
        const float* xb = x + (size_t)b * 3 * NPTS;
        float px = xb[p], py = xb[NPTS + p], pz = xb[2 * NPTS + p];
        g_xp[idx] = make_float4(px, py, pz, -0.5f * (px*px + py*py + pz*pz));
    }
    if (blockIdx.x == 0 && threadIdx.x < CO) {
        int o = threadIdx.x;
        float inv   = gamma_[o] * rsqrtf(var_[o] + 1e-5f);
        float shift = beta_[o] - mean_[o] * inv;
        g_wf[2*o]   = make_float4(W[6*o+0], W[6*o+1], W[6*o+2], W[6*o+3]);
        g_wf[2*o+1] = make_float4(W[6*o+4], W[6*o+5], inv, shift);
    }
}

// key: monotone-uint of pd/2 = dot(q,p) - (|q|^2+|p|^2)/2. Bit-exact on recompute.
__device__ __forceinline__ unsigned keyof(const float4& q, const float4& v)
{
    float s = q.w + v.w;
    s = fmaf(q.x, v.x, fmaf(q.y, v.y, fmaf(q.z, v.z, s)));
    unsigned bb = __float_as_uint(s);
    return bb ^ (unsigned)(((int)bb >> 31) | 0x80000000);
}

__global__ __launch_bounds__(CTA)
void edgeconv_kernel(float* __restrict__ out)
{
    __shared__ int            hist[256];
    __shared__ int            warpTot[8], warpOff[8];
    __shared__ unsigned       ckey[CAP];            // 8 KB
    __shared__ unsigned short cidx[CAP];            // 4 KB
    __shared__ int            knn_s[KNN];
    __shared__ float4         nbr[KNN];
    __shared__ unsigned       tie_key[TIE_CAP];
    __shared__ unsigned short tie_idx[TIE_CAP];
    __shared__ int s_cntC, s_cntW, s_cntT, s_need, s_cnt, s_shift, s_pb;
    __shared__ unsigned s_prefix;

    const int b    = blockIdx.y;
    const int n    = blockIdx.x;
    const int tid  = threadIdx.x;
    const int lane = tid & 31;
    const int wid  = tid >> 5;
    unsigned lt_mask; asm("mov.u32 %0, %%lanemask_lt;" : "=r"(lt_mask));

    const float4* __restrict__ xp = g_xp + (size_t)b * NPTS;
    const float4 q = xp[n];

    hist[tid] = 0;
    if (tid == 0) { s_cntC = 0; s_cntW = 0; s_cntT = 0; s_need = KNN; s_cnt = 0; s_shift = 24; }
    __syncthreads();

    // ---- phase A: calibration — first 512 keys, full match-aggregated hist insert
    #pragma unroll
    for (int i = 0; i < PREI; i++) {
        unsigned u = keyof(q, xp[i * CTA + tid]);
        int bin = (int)(u >> 24);
        unsigned mk = __match_any_sync(0xffffffffu, bin);
        if (!(mk & lt_mask)) atomicAdd(&hist[bin], __popc(mk));
    }
    __syncthreads();

    // ---- provisional threshold pb (exact lower bound on final threshold bin)
    {
        int binv = hist[255 - tid];
        int cum = binv;
        #pragma unroll
        for (int off = 1; off < 32; off <<= 1) {
            int t = __shfl_up_sync(0xffffffffu, cum, off);
            if (lane >= off) cum += t;
        }
        if (lane == 31) warpTot[wid] = cum;
        __syncthreads();
        if (wid == 0) {
            int v = (lane < 8) ? warpTot[lane] : 0;
            int cc = v;
            #pragma unroll
            for (int off = 1; off < 8; off <<= 1) {
                int t = __shfl_up_sync(0xffffffffu, cc, off);
                if (lane >= off) cc += t;
            }
            if (lane < 8) warpOff[lane] = cc - v;
        }
        __syncthreads();
        int cumAll    = cum + warpOff[wid];
        int cumBefore = cumAll - binv;
        if (cumBefore < KNN && KNN <= cumAll) s_pb = 255 - tid;
        __syncthreads();
    }
    const int pb = s_pb;

    // ---- phase B: main sweep — hist insert + candidate append for bins >= pb
    #pragma unroll
    for (int i = PREI; i < ITER; i++) {
        int p = i * CTA + tid;
        unsigned u = keyof(q, xp[p]);
        int bin = (int)(u >> 24);
        if (bin >= pb) {
            atomicAdd(&hist[bin], 1);
            int pos = atomicAdd(&s_cntC, 1);
            if (pos < CAP) { ckey[pos] = u; cidx[pos] = (unsigned short)p; }
        }
    }
    // ---- phase B2: calibration points' candidates (hist already counted)
    #pragma unroll
    for (int i = 0; i < PREI; i++) {
        int p = i * CTA + tid;
        unsigned u = keyof(q, xp[p]);
        int bin = (int)(u >> 24);
        if (bin >= pb) {
            int pos = atomicAdd(&s_cntC, 1);
            if (pos < CAP) { ckey[pos] = u; cidx[pos] = (unsigned short)p; }
        }
    }
    __syncthreads();

    // ---- final threshold: full suffix scan (bins >= pb are exact; threshold >= pb)
    {
        int binv = hist[255 - tid];
        int cum = binv;
        #pragma unroll
        for (int off = 1; off < 32; off <<= 1) {
            int t = __shfl_up_sync(0xffffffffu, cum, off);
            if (lane >= off) cum += t;
        }
        if (lane == 31) warpTot[wid] = cum;
        __syncthreads();
        if (wid == 0) {
            int v = (lane < 8) ? warpTot[lane] : 0;
            int cc = v;
            #pragma unroll
            for (int off = 1; off < 8; off <<= 1) {
                int t = __shfl_up_sync(0xffffffffu, cc, off);
                if (lane >= off) cc += t;
            }
            if (lane < 8) warpOff[lane] = cc - v;
        }
        __syncthreads();
        int cumAll    = cum + warpOff[wid];
        int cumBefore = cumAll - binv;
        if (cumBefore < KNN && KNN <= cumAll) {
            s_prefix = (unsigned)(255 - tid);
            s_need   = KNN - cumBefore;
            s_cnt    = binv;
        }
    }
    __syncthreads();

    const bool ovf = (s_cntC > CAP);
    const int  nC  = ovf ? 0 : s_cntC;

    // ---- refine while threshold-bin population > TIE_CAP (snapshot-disciplined)
    while (s_cnt > TIE_CAP && s_shift > 0) {
        const unsigned pf    = s_prefix;
        const int      sh    = s_shift;
        const int      nsh   = sh - 8;
        const int      needv = s_need;
        __syncthreads();
        hist[tid] = 0;
        __syncthreads();
        if (!ovf) {
            for (int e = tid; e < nC; e += CTA) {
                unsigned u = ckey[e];
                if ((u >> sh) == pf) atomicAdd(&hist[(u >> nsh) & 255u], 1);
            }
        } else {
            #pragma unroll
            for (int i = 0; i < ITER; i++) {
                unsigned u = keyof(q, xp[i * CTA + tid]);
                if ((u >> sh) == pf) atomicAdd(&hist[(u >> nsh) & 255u], 1);
            }
        }
        __syncthreads();
        {
            int binv = hist[255 - tid];
            int cum = binv;
            #pragma unroll
            for (int off = 1; off < 32; off <<= 1) {
                int t = __shfl_up_sync(0xffffffffu, cum, off);
                if (lane >= off) cum += t;
            }
            if (lane == 31) warpTot[wid] = cum;
            __syncthreads();
            if (wid == 0) {
                int v = (lane < 8) ? warpTot[lane] : 0;
                int cc = v;
                #pragma unroll
                for (int off = 1; off < 8; off <<= 1) {
                    int t = __shfl_up_sync(0xffffffffu, cc, off);
                    if (lane >= off) cc += t;
                }
                if (lane < 8) warpOff[lane] = cc - v;
            }
            __syncthreads();
            int cumAll    = cum + warpOff[wid];
            int cumBefore = cumAll - binv;
            if (cumBefore < needv && needv <= cumAll) {
                s_prefix = (pf << 8) | (unsigned)(255 - tid);
                s_need   = needv - cumBefore;
                s_cnt    = binv;
                s_shift  = nsh;
            }
        }
        __syncthreads();
    }

    // ---- collect winners + boundary-bin ties
    {
        const int      sh = s_shift;
        const unsigned pf = s_prefix;
        if (!ovf) {
            for (int e = tid; e < nC; e += CTA) {
                unsigned u  = ckey[e];
                unsigned hi = u >> sh;
                if (hi >= pf) {
                    if (hi > pf) {
                        knn_s[atomicAdd(&s_cntW, 1)] = cidx[e];
                    } else {
                        int pos = atomicAdd(&s_cntT, 1);
                        if (pos < TIE_CAP) { tie_key[pos] = u; tie_idx[pos] = cidx[e]; }
                    }
                }
            }
        } else {
            #pragma unroll
            for (int i = 0; i < ITER; i++) {
                int p = i * CTA + tid;
                unsigned u  = keyof(q, xp[p]);
                unsigned hi = u >> sh;
                if (hi >= pf) {
                    if (hi > pf) {
                        knn_s[atomicAdd(&s_cntW, 1)] = p;
                    } else {
                        int pos = atomicAdd(&s_cntT, 1);
                        if (pos < TIE_CAP) { tie_key[pos] = u; tie_idx[pos] = (unsigned short)p; }
                    }
                }
            }
        }
    }
    __syncthreads();

    // ---- parallel exact tie resolve: rank by (value desc, index asc)
    {
        int cnt   = s_cntT < TIE_CAP ? s_cntT : TIE_CAP;
        int needf = s_need;
        int baseW = s_cntW;
        if (tid < cnt) {
            unsigned mk = tie_key[tid]; int mi = tie_idx[tid];
            int rank = 0;
            for (int j = 0; j < cnt; j++) {
                unsigned kj = tie_key[j]; int ij = tie_idx[j];
                rank += (kj > mk) || (kj == mk && ij < mi);
            }
            if (rank < needf) knn_s[baseW + rank] = mi;
        }
    }
    __syncthreads();

    // ---- gather neighbor coords
    if (tid < KNN) nbr[tid] = xp[knn_s[tid]];
    __syncthreads();

    // ---- edge MLP: 4 threads per output channel, 5 k's each, shfl-combine
    {
        const int o = tid >> 2;
        const int c = tid & 3;
        const float4 wa = g_wf[2*o];      // w0 w1 w2 w3
        const float4 wb = g_wf[2*o + 1];  // w4 w5 inv shift
        const float cpart = fmaf(q.x, wa.w, fmaf(q.y, wb.x, q.z * wb.y));

        float m = -3.4028235e38f;
        #pragma unroll
        for (int k = 0; k < 5; k++) {
            float4 p = nbr[c * 5 + k];
            float y = fmaf(p.x - q.x, wa.x,
                      fmaf(p.y - q.y, wa.y,
                      fmaf(p.z - q.z, wa.z, cpart)));
            y = fmaf(y, wb.z, wb.w);
            y = (y >= 0.0f) ? y : 0.2f * y;
            m = fmaxf(m, y);
        }
        m = fmaxf(m, __shfl_xor_sync(0xffffffffu, m, 1));
        m = fmaxf(m, __shfl_xor_sync(0xffffffffu, m, 2));
        if (c == 0)
            out[(size_t)b * CO * NPTS + (size_t)o * NPTS + n] = m;
    }
}

extern "C" void kernel_launch(void* const* d_in, const int* in_sizes, int n_in,
                              void* d_out, int out_size)
{
    const float* x      = (const float*)d_in[0];
    const float* W      = (const float*)d_in[1];
    const float* gamma_ = (const float*)d_in[2];
    const float* beta_  = (const float*)d_in[3];
    const float* mean_  = (const float*)d_in[4];
    const float* var_   = (const float*)d_in[5];
    float* out = (float*)d_out;

    prep_kernel<<<(NB * NPTS + 255) / 256, 256>>>(x, W, gamma_, beta_, mean_, var_);
    dim3 grid(NPTS, NB);
    edgeconv_kernel<<<grid, CTA>>>(out);
}